// round 3
// baseline (speedup 1.0000x reference)
#include <cuda_runtime.h>
#include <math.h>

#define BATCH  4
#define SEQ    2048
#define DMODEL 1024
#define NHEAD  16
#define DHEAD  64
#define MROWS  (BATCH * SEQ)   // 8192

// Scratch (device globals: allocation-free)
__device__ float g_q[(size_t)BATCH * NHEAD * SEQ * DHEAD];
__device__ float g_k[(size_t)BATCH * NHEAD * SEQ * DHEAD];
__device__ float g_v[(size_t)BATCH * NHEAD * SEQ * DHEAD];
__device__ float g_attn[(size_t)BATCH * SEQ * DMODEL];

// ---------------------------------------------------------------------------
// GEMM: out[8192,1024] = A[8192,1024] @ W[1024,1024] + bias
// BM=128, BN=64, BK=16, 256 threads, 8x4 per-thread microtile.
// mode 0/1/2: store head-split layout into g_q/g_k/g_v.  mode 3: A = g_attn,
// plain row-major store into outp.
// ---------------------------------------------------------------------------
__global__ __launch_bounds__(256) void gemm_kernel(
    const float* __restrict__ Ain, const float* __restrict__ W,
    const float* __restrict__ bias, float* __restrict__ outp, int mode)
{
    __shared__ float As[16][128];   // k-major
    __shared__ float Bs[16][64];

    const float* A = (mode == 3) ? g_attn : Ain;

    const int tid = threadIdx.x;
    const int tx  = tid & 15;       // col group (4 cols)
    const int ty  = tid >> 4;       // row group (8 rows)
    const int m0  = blockIdx.y * 128;
    const int n0  = blockIdx.x * 64;

    float acc[8][4];
#pragma unroll
    for (int i = 0; i < 8; ++i)
#pragma unroll
        for (int j = 0; j < 4; ++j) acc[i][j] = 0.0f;

    for (int k0 = 0; k0 < DMODEL; k0 += 16) {
        // A tile: 128 rows x 16 k  (512 float4, 2 per thread), store k-major
#pragma unroll
        for (int it = 0; it < 2; ++it) {
            int f  = tid + it * 256;
            int r  = f >> 2;
            int kq = f & 3;
            float4 v = *(const float4*)(A + (size_t)(m0 + r) * DMODEL + k0 + kq * 4);
            As[kq * 4 + 0][r] = v.x;
            As[kq * 4 + 1][r] = v.y;
            As[kq * 4 + 2][r] = v.z;
            As[kq * 4 + 3][r] = v.w;
        }
        // B tile: 16 k x 64 n (256 float4, 1 per thread)
        {
            float4 v = *(const float4*)(W + (size_t)(k0 + ty) * DMODEL + n0 + tx * 4);
            *(float4*)&Bs[ty][tx * 4] = v;
        }
        __syncthreads();

#pragma unroll
        for (int k = 0; k < 16; ++k) {
            float4 a0 = *(const float4*)&As[k][ty * 8];
            float4 a1 = *(const float4*)&As[k][ty * 8 + 4];
            float4 b4 = *(const float4*)&Bs[k][tx * 4];
            float a[8] = {a0.x, a0.y, a0.z, a0.w, a1.x, a1.y, a1.z, a1.w};
            float b[4] = {b4.x, b4.y, b4.z, b4.w};
#pragma unroll
            for (int i = 0; i < 8; ++i)
#pragma unroll
                for (int j = 0; j < 4; ++j)
                    acc[i][j] += a[i] * b[j];
        }
        __syncthreads();
    }

    float4 bi = *(const float4*)(bias + n0 + tx * 4);

    if (mode == 3) {
#pragma unroll
        for (int i = 0; i < 8; ++i) {
            int m = m0 + ty * 8 + i;
            float4 o = make_float4(acc[i][0] + bi.x, acc[i][1] + bi.y,
                                   acc[i][2] + bi.z, acc[i][3] + bi.w);
            *(float4*)(outp + (size_t)m * DMODEL + n0 + tx * 4) = o;
        }
    } else {
        float* out = (mode == 0) ? g_q : (mode == 1) ? g_k : g_v;
        int h = blockIdx.x;  // BN==DHEAD: one head per column tile
#pragma unroll
        for (int i = 0; i < 8; ++i) {
            int m = m0 + ty * 8 + i;
            int b = m >> 11;       // /SEQ
            int n = m & 2047;      // %SEQ
            float4 o = make_float4(acc[i][0] + bi.x, acc[i][1] + bi.y,
                                   acc[i][2] + bi.z, acc[i][3] + bi.w);
            *(float4*)(out + ((size_t)(b * NHEAD + h) * SEQ + n) * DHEAD + tx * 4) = o;
        }
    }
}

// ---------------------------------------------------------------------------
// Causal flash attention, fp32. One block = one (b,h) and one 64-query tile.
// 256 threads; per-thread 4x4 microtile of the 64x64 S / O tiles.
// Dynamic smem: Qs[64][64] (d-major), KP[64*68] (K d-major, then P r-major),
// Vs[64][64] (natural). 50176 bytes.
// ---------------------------------------------------------------------------
#define ATTN_SMEM_BYTES ((64 * 64 + 64 * 68 + 64 * 64) * 4)

__global__ __launch_bounds__(256) void attn_kernel()
{
    extern __shared__ float sm[];
    float* Qs = sm;                     // [d][r]  stride 64
    float* KP = sm + 64 * 64;           // stride 68 (K: [d][kc], later P: [r][k])
    float* Vs = sm + 64 * 64 + 64 * 68; // [k][c]  stride 64

    const int qt  = 31 - blockIdx.x;    // heavy tiles first
    const int bh  = blockIdx.y;
    const int tid = threadIdx.x;
    const int tx  = tid & 15;
    const int ty  = tid >> 4;

    const float* qp = g_q + ((size_t)bh * SEQ + (size_t)qt * 64) * DHEAD;
    const float* kb = g_k + (size_t)bh * SEQ * DHEAD;
    const float* vb = g_v + (size_t)bh * SEQ * DHEAD;

    // Load Q (scaled by 1/sqrt(DH)=0.125), transpose to d-major
#pragma unroll
    for (int it = 0; it < 4; ++it) {
        int f  = tid + it * 256;
        int r  = f >> 4;
        int dq = f & 15;
        float4 v = ((const float4*)qp)[f];
        Qs[(dq * 4 + 0) * 64 + r] = v.x * 0.125f;
        Qs[(dq * 4 + 1) * 64 + r] = v.y * 0.125f;
        Qs[(dq * 4 + 2) * 64 + r] = v.z * 0.125f;
        Qs[(dq * 4 + 3) * 64 + r] = v.w * 0.125f;
    }

    float m_i[4], l_i[4], O[4][4];
#pragma unroll
    for (int i = 0; i < 4; ++i) {
        m_i[i] = -1e30f;
        l_i[i] = 0.0f;
#pragma unroll
        for (int j = 0; j < 4; ++j) O[i][j] = 0.0f;
    }

    for (int kt = 0; kt <= qt; ++kt) {
        __syncthreads();  // previous tile's P/V reads done before overwrite
        const float4* kp = (const float4*)(kb + (size_t)kt * 64 * DHEAD);
        const float4* vp = (const float4*)(vb + (size_t)kt * 64 * DHEAD);
#pragma unroll
        for (int it = 0; it < 4; ++it) {
            int f  = tid + it * 256;
            int r  = f >> 4;
            int dq = f & 15;
            float4 v = kp[f];
            KP[(dq * 4 + 0) * 68 + r] = v.x;
            KP[(dq * 4 + 1) * 68 + r] = v.y;
            KP[(dq * 4 + 2) * 68 + r] = v.z;
            KP[(dq * 4 + 3) * 68 + r] = v.w;
            ((float4*)Vs)[f] = vp[f];
        }
        __syncthreads();

        // S = Q * K^T  (64x64x64)
        float s[4][4];
#pragma unroll
        for (int i = 0; i < 4; ++i)
#pragma unroll
            for (int j = 0; j < 4; ++j) s[i][j] = 0.0f;

#pragma unroll 8
        for (int d = 0; d < 64; ++d) {
            float4 q4 = *(const float4*)&Qs[d * 64 + ty * 4];
            float4 k4 = *(const float4*)&KP[d * 68 + tx * 4];
            float qa[4] = {q4.x, q4.y, q4.z, q4.w};
            float ka[4] = {k4.x, k4.y, k4.z, k4.w};
#pragma unroll
            for (int i = 0; i < 4; ++i)
#pragma unroll
                for (int j = 0; j < 4; ++j)
                    s[i][j] += qa[i] * ka[j];
        }

        if (kt == qt) {  // diagonal tile: mask key > query
#pragma unroll
            for (int i = 0; i < 4; ++i)
#pragma unroll
                for (int j = 0; j < 4; ++j)
                    if (tx * 4 + j > ty * 4 + i) s[i][j] = -1e30f;
        }

        // Online softmax (rows owned by 16 consecutive lanes sharing ty)
        float al[4];
#pragma unroll
        for (int i = 0; i < 4; ++i) {
            float pm = fmaxf(fmaxf(s[i][0], s[i][1]), fmaxf(s[i][2], s[i][3]));
            pm = fmaxf(pm, __shfl_xor_sync(0xffffffffu, pm, 1));
            pm = fmaxf(pm, __shfl_xor_sync(0xffffffffu, pm, 2));
            pm = fmaxf(pm, __shfl_xor_sync(0xffffffffu, pm, 4));
            pm = fmaxf(pm, __shfl_xor_sync(0xffffffffu, pm, 8));
            float mn = fmaxf(m_i[i], pm);
            al[i] = __expf(m_i[i] - mn);
            m_i[i] = mn;
            float rs = 0.0f;
#pragma unroll
            for (int j = 0; j < 4; ++j) {
                s[i][j] = __expf(s[i][j] - mn);
                rs += s[i][j];
            }
            rs += __shfl_xor_sync(0xffffffffu, rs, 1);
            rs += __shfl_xor_sync(0xffffffffu, rs, 2);
            rs += __shfl_xor_sync(0xffffffffu, rs, 4);
            rs += __shfl_xor_sync(0xffffffffu, rs, 8);
            l_i[i] = l_i[i] * al[i] + rs;
#pragma unroll
            for (int j = 0; j < 4; ++j) O[i][j] *= al[i];
        }

        __syncthreads();  // all K reads done before P overwrites KP
#pragma unroll
        for (int i = 0; i < 4; ++i)
#pragma unroll
            for (int j = 0; j < 4; ++j)
                KP[(ty * 4 + i) * 68 + tx * 4 + j] = s[i][j];
        __syncthreads();

        // O += P * V
#pragma unroll 8
        for (int k = 0; k < 64; ++k) {
            float4 v4 = *(const float4*)&Vs[k * 64 + tx * 4];
#pragma unroll
            for (int i = 0; i < 4; ++i) {
                float p = KP[(ty * 4 + i) * 68 + k];
                O[i][0] += p * v4.x;
                O[i][1] += p * v4.y;
                O[i][2] += p * v4.z;
                O[i][3] += p * v4.w;
            }
        }
    }

    // Epilogue: normalize and store to (b, n, d) layout
    const int b = bh >> 4;
    const int h = bh & 15;
#pragma unroll
    for (int i = 0; i < 4; ++i) {
        int r = ty * 4 + i;
        float inv = 1.0f / l_i[i];
        float4 o = make_float4(O[i][0] * inv, O[i][1] * inv,
                               O[i][2] * inv, O[i][3] * inv);
        *(float4*)(g_attn + ((size_t)b * SEQ + (size_t)qt * 64 + r) * DMODEL
                   + h * DHEAD + tx * 4) = o;
    }
}

// ---------------------------------------------------------------------------
extern "C" void kernel_launch(void* const* d_in, const int* in_sizes, int n_in,
                              void* d_out, int out_size)
{
    const float* x  = (const float*)d_in[0];
    const float* Wq = (const float*)d_in[1];
    const float* bq = (const float*)d_in[2];
    const float* Wk = (const float*)d_in[3];
    const float* bk = (const float*)d_in[4];
    const float* Wv = (const float*)d_in[5];
    const float* bv = (const float*)d_in[6];
    const float* Wo = (const float*)d_in[7];
    const float* bo = (const float*)d_in[8];

    cudaFuncSetAttribute(attn_kernel,
                         cudaFuncAttributeMaxDynamicSharedMemorySize,
                         ATTN_SMEM_BYTES);

    dim3 gg(DMODEL / 64, MROWS / 128);  // (16, 64)
    dim3 tb(256);

    gemm_kernel<<<gg, tb>>>(x, Wq, bq, nullptr, 0);
    gemm_kernel<<<gg, tb>>>(x, Wk, bk, nullptr, 1);
    gemm_kernel<<<gg, tb>>>(x, Wv, bv, nullptr, 2);
    attn_kernel<<<dim3(SEQ / 64, BATCH * NHEAD), tb, ATTN_SMEM_BYTES>>>();
    gemm_kernel<<<gg, tb>>>(nullptr, Wo, bo, (float*)d_out, 3);
}

// round 5
// speedup vs baseline: 3.9331x; 3.9331x over previous
#include <cuda_runtime.h>
#include <math.h>

#define SEQ 2048
#define DM  1024
#define NH  16
#define DH  64
#define BATCH 4
#define MROWS (BATCH * SEQ)          // 8192

// log2(e) * (1/sqrt(64)) folded into Q so softmax uses ex2 directly
#define QSCALE 0.1803368801111204f

// Scratch (device globals: allocation-free)
__device__ float g_q[(size_t)BATCH * NH * SEQ * DH];     // [bh][seq][dh]
__device__ float g_k[(size_t)BATCH * NH * DH * SEQ];     // [bh][dh][seq]  (TRANSPOSED)
__device__ float g_v[(size_t)BATCH * NH * SEQ * DH];     // [bh][seq][dh]
__device__ float g_attn[(size_t)BATCH * SEQ * DM];       // [b][seq][dm]

// ---------------------------------------------------------------------------
// helpers
// ---------------------------------------------------------------------------
__device__ __forceinline__ float tf32f(float x) {
    unsigned u; asm("cvt.rna.tf32.f32 %0, %1;" : "=r"(u) : "f"(x));
    return __uint_as_float(u);
}
__device__ __forceinline__ unsigned fu(float x) { return __float_as_uint(x); }
__device__ __forceinline__ float ex2f_(float x) {
    float y; asm("ex2.approx.f32 %0, %1;" : "=f"(y) : "f"(x)); return y;
}
__device__ __forceinline__ float rcpf_(float x) {
    float y; asm("rcp.approx.f32 %0, %1;" : "=f"(y) : "f"(x)); return y;
}
__device__ __forceinline__ void mma8(float* c, const unsigned* a,
                                     unsigned b0, unsigned b1) {
    asm volatile(
        "mma.sync.aligned.m16n8k8.row.col.f32.tf32.tf32.f32 "
        "{%0,%1,%2,%3}, {%4,%5,%6,%7}, {%8,%9}, {%0,%1,%2,%3};"
        : "+f"(c[0]), "+f"(c[1]), "+f"(c[2]), "+f"(c[3])
        : "r"(a[0]), "r"(a[1]), "r"(a[2]), "r"(a[3]), "r"(b0), "r"(b1));
}

// ---------------------------------------------------------------------------
// GEMM core: 128x128 block tile, BK=32, 256 threads, 8 warps (2m x 4n),
// warp tile 64x32 (4 m16-tiles x 4 n8-tiles). A staged k-major [k][132],
// B staged [k][132]. Fragments conflict-free.
// ---------------------------------------------------------------------------
__device__ __forceinline__ void gemm_core(
    const float* __restrict__ A, const float* __restrict__ W,
    int m0, int n0, float acc[4][4][4], float* As, float* Bs, int tid)
{
    const int l  = tid & 31;
    const int w  = tid >> 5;
    const int lq = l >> 2, lr = l & 3;
    const int wm = w & 1, wn = w >> 1;

    for (int k0 = 0; k0 < DM; k0 += 32) {
        // stage A: 128x32, transpose to [k][m] (stride 132)
#pragma unroll
        for (int it = 0; it < 4; ++it) {
            int f = tid + it * 256;          // 0..1023
            int r = f >> 3, kq = f & 7;
            float4 x = *(const float4*)(A + (size_t)(m0 + r) * DM + k0 + kq * 4);
            As[(kq * 4 + 0) * 132 + r] = tf32f(x.x);
            As[(kq * 4 + 1) * 132 + r] = tf32f(x.y);
            As[(kq * 4 + 2) * 132 + r] = tf32f(x.z);
            As[(kq * 4 + 3) * 132 + r] = tf32f(x.w);
        }
        // stage B: 32x128 natural [k][n] (stride 132)
#pragma unroll
        for (int it = 0; it < 4; ++it) {
            int f = tid + it * 256;          // 0..1023
            int kk = f >> 5, nq = f & 31;
            float4 x = *(const float4*)(W + (size_t)(k0 + kk) * DM + n0 + nq * 4);
            float4 t = make_float4(tf32f(x.x), tf32f(x.y), tf32f(x.z), tf32f(x.w));
            *(float4*)&Bs[kk * 132 + nq * 4] = t;
        }
        __syncthreads();

#pragma unroll
        for (int ks = 0; ks < 4; ++ks) {
            const int kk = ks * 8;
            unsigned a[4][4], b[4][2];
#pragma unroll
            for (int mt = 0; mt < 4; ++mt) {
                int row = wm * 64 + mt * 16 + lq;
                a[mt][0] = fu(As[(kk + lr) * 132 + row]);
                a[mt][1] = fu(As[(kk + lr) * 132 + row + 8]);
                a[mt][2] = fu(As[(kk + 4 + lr) * 132 + row]);
                a[mt][3] = fu(As[(kk + 4 + lr) * 132 + row + 8]);
            }
#pragma unroll
            for (int nt = 0; nt < 4; ++nt) {
                int col = wn * 32 + nt * 8 + lq;
                b[nt][0] = fu(Bs[(kk + lr) * 132 + col]);
                b[nt][1] = fu(Bs[(kk + 4 + lr) * 132 + col]);
            }
#pragma unroll
            for (int mt = 0; mt < 4; ++mt)
#pragma unroll
                for (int nt = 0; nt < 4; ++nt)
                    mma8(acc[mt][nt], a[mt], b[nt][0], b[nt][1]);
        }
        __syncthreads();
    }
}

// ---------------------------------------------------------------------------
// QKV projections fused: blockIdx.z selects Q/K/V. K stored transposed.
// ---------------------------------------------------------------------------
__global__ __launch_bounds__(256, 2) void qkv_kernel(
    const float* __restrict__ x,
    const float* __restrict__ Wq, const float* __restrict__ bq,
    const float* __restrict__ Wk, const float* __restrict__ bk,
    const float* __restrict__ Wv, const float* __restrict__ bv)
{
    __shared__ float As[32 * 132];
    __shared__ float Bs[32 * 132];

    const int mode = blockIdx.z;
    const float* W  = (mode == 0) ? Wq : (mode == 1) ? Wk : Wv;
    const float* bi = (mode == 0) ? bq : (mode == 1) ? bk : bv;

    const int tid = threadIdx.x;
    const int m0 = blockIdx.y * 128;
    const int n0 = blockIdx.x * 128;

    float acc[4][4][4];
#pragma unroll
    for (int mt = 0; mt < 4; ++mt)
#pragma unroll
        for (int nt = 0; nt < 4; ++nt)
#pragma unroll
            for (int c = 0; c < 4; ++c) acc[mt][nt][c] = 0.0f;

    gemm_core(x, W, m0, n0, acc, As, Bs, tid);

    const int l = tid & 31, w = tid >> 5;
    const int lq = l >> 2, lr = l & 3;
    const int wm = w & 1, wn = w >> 1;

#pragma unroll
    for (int mt = 0; mt < 4; ++mt) {
        int mrow = m0 + wm * 64 + mt * 16 + lq;
        int bb = mrow >> 11;
        int ns = mrow & 2047;
#pragma unroll
        for (int nt = 0; nt < 4; ++nt) {
            int col = n0 + wn * 32 + nt * 8 + 2 * lr;
            float2 bx = *(const float2*)(bi + col);
            float v0 = acc[mt][nt][0] + bx.x;
            float v1 = acc[mt][nt][1] + bx.y;
            float v2 = acc[mt][nt][2] + bx.x;
            float v3 = acc[mt][nt][3] + bx.y;
            int h = col >> 6, d = col & 63;
            if (mode == 1) {
                float* o = g_k + ((size_t)(bb * NH + h) * DH + d) * SEQ;
                o[ns]            = v0;
                o[SEQ + ns]      = v1;
                o[ns + 8]        = v2;
                o[SEQ + ns + 8]  = v3;
            } else {
                float* o = ((mode == 0) ? g_q : g_v)
                         + ((size_t)(bb * NH + h) * SEQ + ns) * DH + d;
                *(float2*)o              = make_float2(v0, v1);
                *(float2*)(o + 8 * DH)   = make_float2(v2, v3);
            }
        }
    }
}

// ---------------------------------------------------------------------------
// Output projection: A = g_attn, row-major store to d_out.
// ---------------------------------------------------------------------------
__global__ __launch_bounds__(256, 2) void oproj_kernel(
    const float* __restrict__ Wo, const float* __restrict__ bo,
    float* __restrict__ outp)
{
    __shared__ float As[32 * 132];
    __shared__ float Bs[32 * 132];

    const int tid = threadIdx.x;
    const int m0 = blockIdx.y * 128;
    const int n0 = blockIdx.x * 128;

    float acc[4][4][4];
#pragma unroll
    for (int mt = 0; mt < 4; ++mt)
#pragma unroll
        for (int nt = 0; nt < 4; ++nt)
#pragma unroll
            for (int c = 0; c < 4; ++c) acc[mt][nt][c] = 0.0f;

    gemm_core(g_attn, Wo, m0, n0, acc, As, Bs, tid);

    const int l = tid & 31, w = tid >> 5;
    const int lq = l >> 2, lr = l & 3;
    const int wm = w & 1, wn = w >> 1;

#pragma unroll
    for (int mt = 0; mt < 4; ++mt) {
        int mrow = m0 + wm * 64 + mt * 16 + lq;
#pragma unroll
        for (int nt = 0; nt < 4; ++nt) {
            int col = n0 + wn * 32 + nt * 8 + 2 * lr;
            float2 bx = *(const float2*)(bo + col);
            *(float2*)(outp + (size_t)mrow * DM + col) =
                make_float2(acc[mt][nt][0] + bx.x, acc[mt][nt][1] + bx.y);
            *(float2*)(outp + (size_t)(mrow + 8) * DM + col) =
                make_float2(acc[mt][nt][2] + bx.x, acc[mt][nt][3] + bx.y);
        }
    }
}

// ---------------------------------------------------------------------------
// Causal flash attention (tf32 mma). Block = 128 queries of one (b,h).
// 8 warps, warp owns 16 q-rows x all 64 keys of the tile.
// Q fragments in registers; K tile [d][key] (from pre-transposed g_k);
// P round-trips through smem (aliases K region). log2-domain softmax.
// smem: KP 128*68 + Vs 64*68 floats = 52224 B.
// ---------------------------------------------------------------------------
#define ATTN_SMEM ((128 * 68 + 64 * 68) * 4)

__global__ __launch_bounds__(256, 2) void attn_kernel()
{
    extern __shared__ float sm[];
    float* KP = sm;                 // Q staging -> K tile [d][68] -> P [q][68]
    float* Vs = sm + 128 * 68;      // V tile [key][68]

    const int qb  = 15 - blockIdx.x;      // heavy tiles first
    const int bh  = blockIdx.y;
    const int tid = threadIdx.x;
    const int w   = tid >> 5;
    const int l   = tid & 31;
    const int lq  = l >> 2, lr = l & 3;
    const int r0  = w * 16 + lq;          // local q row for c0/c1 (c2/c3: +8)

    const float* qp = g_q + ((size_t)bh * SEQ + (size_t)qb * 128) * DH;
    const float* kT = g_k + (size_t)bh * DH * SEQ;
    const float* vp = g_v + (size_t)bh * SEQ * DH;

    // ---- stage Q (scaled to log2 domain), read fragments into registers ----
#pragma unroll
    for (int it = 0; it < 8; ++it) {
        int f = tid + it * 256;           // 0..2047
        int q = f >> 4, dq = f & 15;
        float4 xx = ((const float4*)qp)[f];
        KP[q * 68 + dq * 4 + 0] = tf32f(xx.x * QSCALE);
        KP[q * 68 + dq * 4 + 1] = tf32f(xx.y * QSCALE);
        KP[q * 68 + dq * 4 + 2] = tf32f(xx.z * QSCALE);
        KP[q * 68 + dq * 4 + 3] = tf32f(xx.w * QSCALE);
    }
    __syncthreads();

    unsigned qa[8][4];
#pragma unroll
    for (int s = 0; s < 8; ++s) {
        qa[s][0] = fu(KP[r0 * 68 + 8 * s + lr]);
        qa[s][1] = fu(KP[(r0 + 8) * 68 + 8 * s + lr]);
        qa[s][2] = fu(KP[r0 * 68 + 8 * s + 4 + lr]);
        qa[s][3] = fu(KP[(r0 + 8) * 68 + 8 * s + 4 + lr]);
    }

    float m0v = -1e30f, m1v = -1e30f, l0v = 0.0f, l1v = 0.0f;
    float o[8][4];
#pragma unroll
    for (int nt = 0; nt < 8; ++nt)
#pragma unroll
        for (int c = 0; c < 4; ++c) o[nt][c] = 0.0f;

    const int ktmax = 2 * qb + 1;
    for (int kt = 0; kt <= ktmax; ++kt) {
        __syncthreads();   // prev iter P/V reads done

        // stage K tile [d][key] and V tile [key][d]
#pragma unroll
        for (int it = 0; it < 4; ++it) {
            int f = tid + it * 256;       // 0..1023
            int a = f >> 4, q = f & 15;
            float4 kx = *(const float4*)(kT + (size_t)a * SEQ + kt * 64 + q * 4);
            KP[a * 68 + q * 4 + 0] = tf32f(kx.x);
            KP[a * 68 + q * 4 + 1] = tf32f(kx.y);
            KP[a * 68 + q * 4 + 2] = tf32f(kx.z);
            KP[a * 68 + q * 4 + 3] = tf32f(kx.w);
            float4 vx = *(const float4*)(vp + (size_t)(kt * 64 + a) * DH + q * 4);
            Vs[a * 68 + q * 4 + 0] = tf32f(vx.x);
            Vs[a * 68 + q * 4 + 1] = tf32f(vx.y);
            Vs[a * 68 + q * 4 + 2] = tf32f(vx.z);
            Vs[a * 68 + q * 4 + 3] = tf32f(vx.w);
        }
        __syncthreads();

        // ---- S = Q K^T ----
        float sc[8][4];
#pragma unroll
        for (int nt = 0; nt < 8; ++nt)
#pragma unroll
            for (int c = 0; c < 4; ++c) sc[nt][c] = 0.0f;

#pragma unroll
        for (int s = 0; s < 8; ++s) {
#pragma unroll
            for (int nt = 0; nt < 8; ++nt) {
                unsigned b0 = fu(KP[(8 * s + lr) * 68 + 8 * nt + lq]);
                unsigned b1 = fu(KP[(8 * s + 4 + lr) * 68 + 8 * nt + lq]);
                mma8(sc[nt], qa[s], b0, b1);
            }
        }

        // ---- causal mask (only possible on last two tiles) ----
        if (kt >= 2 * qb) {
            int qg0 = qb * 128 + r0;
            int qg1 = qg0 + 8;
#pragma unroll
            for (int nt = 0; nt < 8; ++nt) {
                int kg = kt * 64 + 8 * nt + 2 * lr;
                if (kg > qg0)     sc[nt][0] = -1e30f;
                if (kg + 1 > qg0) sc[nt][1] = -1e30f;
                if (kg > qg1)     sc[nt][2] = -1e30f;
                if (kg + 1 > qg1) sc[nt][3] = -1e30f;
            }
        }

        // ---- online softmax (log2 domain), 2 rows per lane ----
        float mx0 = -1e30f, mx1 = -1e30f;
#pragma unroll
        for (int nt = 0; nt < 8; ++nt) {
            mx0 = fmaxf(mx0, fmaxf(sc[nt][0], sc[nt][1]));
            mx1 = fmaxf(mx1, fmaxf(sc[nt][2], sc[nt][3]));
        }
        mx0 = fmaxf(mx0, __shfl_xor_sync(0xffffffffu, mx0, 1));
        mx0 = fmaxf(mx0, __shfl_xor_sync(0xffffffffu, mx0, 2));
        mx1 = fmaxf(mx1, __shfl_xor_sync(0xffffffffu, mx1, 1));
        mx1 = fmaxf(mx1, __shfl_xor_sync(0xffffffffu, mx1, 2));

        float mn0 = fmaxf(m0v, mx0), mn1 = fmaxf(m1v, mx1);
        float al0 = ex2f_(m0v - mn0), al1 = ex2f_(m1v - mn1);
        m0v = mn0; m1v = mn1;

        float rs0 = 0.0f, rs1 = 0.0f;
#pragma unroll
        for (int nt = 0; nt < 8; ++nt) {
            sc[nt][0] = ex2f_(sc[nt][0] - mn0);
            sc[nt][1] = ex2f_(sc[nt][1] - mn0);
            sc[nt][2] = ex2f_(sc[nt][2] - mn1);
            sc[nt][3] = ex2f_(sc[nt][3] - mn1);
            rs0 += sc[nt][0] + sc[nt][1];
            rs1 += sc[nt][2] + sc[nt][3];
        }
        rs0 += __shfl_xor_sync(0xffffffffu, rs0, 1);
        rs0 += __shfl_xor_sync(0xffffffffu, rs0, 2);
        rs1 += __shfl_xor_sync(0xffffffffu, rs1, 1);
        rs1 += __shfl_xor_sync(0xffffffffu, rs1, 2);
        l0v = l0v * al0 + rs0;
        l1v = l1v * al1 + rs1;
#pragma unroll
        for (int nt = 0; nt < 8; ++nt) {
            o[nt][0] *= al0; o[nt][1] *= al0;
            o[nt][2] *= al1; o[nt][3] *= al1;
        }

        __syncthreads();   // all warps done reading K before P overwrites
#pragma unroll
        for (int nt = 0; nt < 8; ++nt) {
            *(float2*)&KP[r0 * 68 + 8 * nt + 2 * lr] =
                make_float2(sc[nt][0], sc[nt][1]);
            *(float2*)&KP[(r0 + 8) * 68 + 8 * nt + 2 * lr] =
                make_float2(sc[nt][2], sc[nt][3]);
        }
        __syncthreads();

        // ---- O += P V ----
#pragma unroll
        for (int s = 0; s < 8; ++s) {
            unsigned pa[4];
            pa[0] = fu(KP[r0 * 68 + 8 * s + lr]);
            pa[1] = fu(KP[(r0 + 8) * 68 + 8 * s + lr]);
            pa[2] = fu(KP[r0 * 68 + 8 * s + 4 + lr]);
            pa[3] = fu(KP[(r0 + 8) * 68 + 8 * s + 4 + lr]);
#pragma unroll
            for (int nt = 0; nt < 8; ++nt) {
                unsigned b0 = fu(Vs[(8 * s + lr) * 68 + 8 * nt + lq]);
                unsigned b1 = fu(Vs[(8 * s + 4 + lr) * 68 + 8 * nt + lq]);
                mma8(o[nt], pa, b0, b1);
            }
        }
    }

    // ---- epilogue ----
    float i0 = rcpf_(l0v), i1 = rcpf_(l1v);
    const int b = bh >> 4, h = bh & 15;
    const int q0 = qb * 128 + r0;
#pragma unroll
    for (int nt = 0; nt < 8; ++nt) {
        int d = h * 64 + 8 * nt + 2 * lr;
        *(float2*)(g_attn + ((size_t)b * SEQ + q0) * DM + d) =
            make_float2(o[nt][0] * i0, o[nt][1] * i0);
        *(float2*)(g_attn + ((size_t)b * SEQ + q0 + 8) * DM + d) =
            make_float2(o[nt][2] * i1, o[nt][3] * i1);
    }
}

// ---------------------------------------------------------------------------
extern "C" void kernel_launch(void* const* d_in, const int* in_sizes, int n_in,
                              void* d_out, int out_size)
{
    const float* x  = (const float*)d_in[0];
    const float* Wq = (const float*)d_in[1];
    const float* bq = (const float*)d_in[2];
    const float* Wk = (const float*)d_in[3];
    const float* bk = (const float*)d_in[4];
    const float* Wv = (const float*)d_in[5];
    const float* bv = (const float*)d_in[6];
    const float* Wo = (const float*)d_in[7];
    const float* bo = (const float*)d_in[8];

    cudaFuncSetAttribute(attn_kernel,
                         cudaFuncAttributeMaxDynamicSharedMemorySize,
                         ATTN_SMEM);

    dim3 tb(256);
    qkv_kernel<<<dim3(DM / 128, MROWS / 128, 3), tb>>>(x, Wq, bq, Wk, bk, Wv, bv);
    attn_kernel<<<dim3(SEQ / 128, BATCH * NH), tb, ATTN_SMEM>>>();
    oproj_kernel<<<dim3(DM / 128, MROWS / 128), tb>>>(Wo, bo, (float*)d_out);
}